// round 1
// baseline (speedup 1.0000x reference)
#include <cuda_runtime.h>
#include <cuda_bf16.h>

// ---------------- problem constants ----------------
#define N_NODES 100000
#define N_EDGES 3200000
#define IN_F    500
#define HID     64
#define OUT_F   64
#define ALPHA   0.1f
#define K_ITERS 10

#define NSCAN_BLOCKS ((N_NODES + 1023) / 1024)   // 98

// ---------------- static device scratch ----------------
__device__ float g_h1[N_NODES * HID];         // relu(x@W1+b1)
__device__ float g_h [N_NODES * OUT_F];       // MLP output
__device__ float g_z0[N_NODES * OUT_F];       // ping
__device__ float g_z1[N_NODES * OUT_F];       // pong
__device__ int   g_deg[N_NODES];
__device__ int   g_off[N_NODES + 1];
__device__ int   g_pos[N_NODES];
__device__ int   g_csr_src[N_EDGES];
__device__ float g_csr_w [N_EDGES];
__device__ int   g_bsum[NSCAN_BLOCKS];

// ---------------- CSR construction ----------------
__global__ void zero_deg_kernel() {
    int i = blockIdx.x * blockDim.x + threadIdx.x;
    if (i < N_NODES) g_deg[i] = 0;
}

__global__ void hist_kernel(const int* __restrict__ dst) {
    int e = blockIdx.x * blockDim.x + threadIdx.x;
    if (e < N_EDGES) atomicAdd(&g_deg[dst[e]], 1);
}

__global__ void scan_local_kernel() {
    __shared__ int s[1024];
    int tid = threadIdx.x;
    int i = blockIdx.x * 1024 + tid;
    int v = (i < N_NODES) ? g_deg[i] : 0;
    s[tid] = v;
    __syncthreads();
    #pragma unroll
    for (int d = 1; d < 1024; d <<= 1) {
        int t = (tid >= d) ? s[tid - d] : 0;
        __syncthreads();
        s[tid] += t;
        __syncthreads();
    }
    if (i < N_NODES) g_off[i] = s[tid] - v;       // exclusive
    if (tid == 1023) g_bsum[blockIdx.x] = s[1023];
}

__global__ void scan_top_kernel() {
    // single thread: 98 elements, negligible
    if (threadIdx.x == 0 && blockIdx.x == 0) {
        int run = 0;
        for (int b = 0; b < NSCAN_BLOCKS; b++) {
            int t = g_bsum[b];
            g_bsum[b] = run;
            run += t;
        }
    }
}

__global__ void scan_add_kernel() {
    int i = blockIdx.x * 1024 + threadIdx.x;
    if (i < N_NODES) {
        int o = g_off[i] + g_bsum[blockIdx.x];
        g_off[i] = o;
        g_pos[i] = o;
    }
    if (blockIdx.x == 0 && threadIdx.x == 0) g_off[N_NODES] = N_EDGES;
}

__global__ void scatter_kernel(const int* __restrict__ src,
                               const int* __restrict__ dst,
                               const float* __restrict__ w) {
    int e = blockIdx.x * blockDim.x + threadIdx.x;
    if (e < N_EDGES) {
        int d = dst[e];
        int p = atomicAdd(&g_pos[d], 1);
        g_csr_src[p] = src[e];
        g_csr_w[p]   = w[e];
    }
}

// ---------------- GEMM: C[n,64] = act(A[n,K] @ W[K,64] + b) ----------------
// 256 threads = 8 warps; block computes 64 rows. Warp w -> rows w*8..w*8+7,
// lane owns columns (lane, lane+32). K tiled by 32.
template <bool RELU>
__global__ __launch_bounds__(256)
void gemm64_kernel(const float* __restrict__ A, const float* __restrict__ W,
                   const float* __restrict__ bias, float* __restrict__ C,
                   int nrows, int K) {
    __shared__ float  xs[64 * 36];        // 64 rows x 32 k, stride 36 (16B aligned)
    __shared__ float2 ws2[32 * 32];       // [kk][lane] = (W[kk][lane], W[kk][lane+32])

    const int tid  = threadIdx.x;
    const int w    = tid >> 5;
    const int lane = tid & 31;
    const int row0 = blockIdx.x * 64;

    float acc0[8], acc1[8];
    #pragma unroll
    for (int r = 0; r < 8; r++) { acc0[r] = 0.f; acc1[r] = 0.f; }

    for (int ko = 0; ko < K; ko += 32) {
        // stage x tile: thread i loads (row i>>5, kk i&31); 32 lanes = 128B coalesced
        #pragma unroll
        for (int i = tid; i < 64 * 32; i += 256) {
            int r  = i >> 5;
            int kk = i & 31;
            int gr = row0 + r;
            int gk = ko + kk;
            xs[r * 36 + kk] = (gr < nrows && gk < K) ? A[(long)gr * K + gk] : 0.f;
        }
        // stage W tile (small, L2-resident)
        #pragma unroll
        for (int i = tid; i < 32 * 32; i += 256) {
            int kk = i >> 5;
            int c  = i & 31;
            int gk = ko + kk;
            float wx = 0.f, wy = 0.f;
            if (gk < K) { wx = W[gk * 64 + c]; wy = W[gk * 64 + c + 32]; }
            ws2[kk * 32 + c] = make_float2(wx, wy);
        }
        __syncthreads();

        #pragma unroll
        for (int kk = 0; kk < 32; kk += 4) {
            float4 xq[8];
            #pragma unroll
            for (int r = 0; r < 8; r++)
                xq[r] = *(const float4*)(xs + (w * 8 + r) * 36 + kk);
            #pragma unroll
            for (int j = 0; j < 4; j++) {
                float2 wv = ws2[(kk + j) * 32 + lane];
                #pragma unroll
                for (int r = 0; r < 8; r++) {
                    float xv = (j == 0) ? xq[r].x : (j == 1) ? xq[r].y
                             : (j == 2) ? xq[r].z : xq[r].w;
                    acc0[r] = fmaf(xv, wv.x, acc0[r]);
                    acc1[r] = fmaf(xv, wv.y, acc1[r]);
                }
            }
        }
        __syncthreads();
    }

    float b0 = bias[lane], b1 = bias[lane + 32];
    #pragma unroll
    for (int r = 0; r < 8; r++) {
        int row = row0 + w * 8 + r;
        if (row < nrows) {
            float c0 = acc0[r] + b0;
            float c1 = acc1[r] + b1;
            if (RELU) { c0 = fmaxf(c0, 0.f); c1 = fmaxf(c1, 0.f); }
            C[row * 64 + lane]      = c0;
            C[row * 64 + lane + 32] = c1;
        }
    }
}

// ---------------- APPNP propagation (pull, warp per node) ----------------
// zout[n][:] = (1-alpha) * sum_e w_e * zin[src_e][:] + alpha * h[n][:]
__global__ __launch_bounds__(256)
void prop_kernel(const float* __restrict__ zin, const float* __restrict__ h,
                 float* __restrict__ zout) {
    int gtid = blockIdx.x * blockDim.x + threadIdx.x;
    int node = gtid >> 5;
    int lane = threadIdx.x & 31;
    if (node >= N_NODES) return;

    int beg = g_off[node];
    int end = g_off[node + 1];

    float a0 = 0.f, a1 = 0.f;
    for (int e = beg; e < end; e += 32) {
        int idx = e + lane;
        int   s = 0;
        float w = 0.f;
        if (idx < end) { s = g_csr_src[idx]; w = g_csr_w[idx]; }
        int rem = end - e;
        int cnt = rem < 32 ? rem : 32;
        #pragma unroll 4
        for (int j = 0; j < cnt; j++) {
            int   sj = __shfl_sync(0xffffffffu, s, j);
            float wj = __shfl_sync(0xffffffffu, w, j);
            const float* zr = zin + (long)sj * 64;
            a0 = fmaf(wj, __ldg(zr + lane),      a0);
            a1 = fmaf(wj, __ldg(zr + lane + 32), a1);
        }
    }
    long o = (long)node * 64;
    zout[o + lane]      = (1.0f - ALPHA) * a0 + ALPHA * h[o + lane];
    zout[o + lane + 32] = (1.0f - ALPHA) * a1 + ALPHA * h[o + lane + 32];
}

// ---------------- launch ----------------
extern "C" void kernel_launch(void* const* d_in, const int* in_sizes, int n_in,
                              void* d_out, int out_size) {
    const float* x   = (const float*)d_in[0];
    const int*   esrc = (const int*)d_in[1];
    const int*   edst = (const int*)d_in[2];
    const float* ew  = (const float*)d_in[3];
    const float* W1  = (const float*)d_in[4];
    const float* b1  = (const float*)d_in[5];
    const float* W2  = (const float*)d_in[6];
    const float* b2  = (const float*)d_in[7];
    float* out = (float*)d_out;

    // --- CSR build (per launch, deterministic sums) ---
    zero_deg_kernel<<<NSCAN_BLOCKS, 1024>>>();
    hist_kernel<<<(N_EDGES + 255) / 256, 256>>>(edst);
    scan_local_kernel<<<NSCAN_BLOCKS, 1024>>>();
    scan_top_kernel<<<1, 32>>>();
    scan_add_kernel<<<NSCAN_BLOCKS, 1024>>>();
    scatter_kernel<<<(N_EDGES + 255) / 256, 256>>>(esrc, edst, ew);

    // --- MLP encoder ---
    // raw pointers to device globals (device-side symbols usable directly in kernels;
    // host side needs addresses only for kernel args)
    float *h1_p, *h_p, *z0_p, *z1_p;
    cudaGetSymbolAddress((void**)&h1_p, g_h1);
    cudaGetSymbolAddress((void**)&h_p,  g_h);
    cudaGetSymbolAddress((void**)&z0_p, g_z0);
    cudaGetSymbolAddress((void**)&z1_p, g_z1);

    int gblocks = (N_NODES + 63) / 64;
    gemm64_kernel<true ><<<gblocks, 256>>>(x,    W1, b1, h1_p, N_NODES, IN_F);
    gemm64_kernel<false><<<gblocks, 256>>>(h1_p, W2, b2, h_p,  N_NODES, HID);

    // --- K propagation steps, last writes d_out ---
    int pblocks = (N_NODES * 32 + 255) / 256;
    const float* zin = h_p;
    for (int k = 0; k < K_ITERS; k++) {
        float* zout = (k == K_ITERS - 1) ? out : ((k & 1) ? z1_p : z0_p);
        prop_kernel<<<pblocks, 256>>>(zin, h_p, zout);
        zin = zout;
    }
}